// round 16
// baseline (speedup 1.0000x reference)
#include <cuda_runtime.h>
#include <cuda_bf16.h>
#include <cstdint>

#define HH   256
#define NN   32
#define LL   4096
#define BB   4
#define NCH  8
#define CLEN 512   // LL / NCH

typedef unsigned long long ull;
typedef unsigned short ush;

// ---------------- device scratch (no allocations allowed) ----------------
__device__ ush g_ahi[(size_t)BB*HH*LL];   // act bf16 hi plane, [b][h][l]
__device__ ush g_alo[(size_t)BB*HH*LL];   // act bf16 lo plane
__device__ ush g_whi[HH*HH];              // W bf16 hi, [o][h]
__device__ ush g_wlo[HH*HH];              // W bf16 lo

// ---------------- packed f32x2 helpers ----------------
__device__ __forceinline__ ull pk(float lo, float hi) {
    ull r;
    asm("mov.b64 %0, {%1, %2};" : "=l"(r)
        : "r"(__float_as_uint(lo)), "r"(__float_as_uint(hi)));
    return r;
}
__device__ __forceinline__ void upk(ull v, float& lo, float& hi) {
    unsigned a, b;
    asm("mov.b64 {%0, %1}, %2;" : "=r"(a), "=r"(b) : "l"(v));
    lo = __uint_as_float(a); hi = __uint_as_float(b);
}
__device__ __forceinline__ ull fma2(ull a, ull b, ull c) {
    ull d;
    asm("fma.rn.f32x2 %0, %1, %2, %3;" : "=l"(d) : "l"(a), "l"(b), "l"(c));
    return d;
}
__device__ __forceinline__ ull mul2(ull a, ull b) {
    ull d;
    asm("mul.rn.f32x2 %0, %1, %2;" : "=l"(d) : "l"(a), "l"(b));
    return d;
}
__device__ __forceinline__ ull add2(ull a, ull b) {
    ull d;
    asm("add.rn.f32x2 %0, %1, %2;" : "=l"(d) : "l"(a), "l"(b));
    return d;
}

__device__ __forceinline__ float gelu_tanh(float x)
{
    float x3 = x * x * x;
    float z  = 0.7978845608028654f * fmaf(0.044715f, x3, x);
    float e  = __expf(2.f * z);
    float t  = 1.f - __fdividef(2.f, e + 1.f);   // tanh(z)
    return 0.5f * x * (1.f + t);
}

__device__ __forceinline__ float warp_sum(float v) {
    #pragma unroll
    for (int m = 16; m >= 1; m >>= 1) v += __shfl_xor_sync(0xffffffffu, v, m);
    return v;
}

__device__ __forceinline__ uint32_t smem_u32(const void* p) {
    uint32_t a;
    asm("{ .reg .u64 t; cvta.to.shared.u64 t, %1; cvt.u32.u64 %0, t; }"
        : "=r"(a) : "l"(p));
    return a;
}

// ---------------- fused scan + W split + D + liquid + gelu ----------------
// SMEM: u (4096 f) | q (8 warps * 1056 f) | carry 512 | initv 512 = 54272 B
__global__ void __launch_bounds__(256, 4) scan_kernel(
    const float* __restrict__ u,
    const float* __restrict__ log_dt,
    const float* __restrict__ w_re, const float* __restrict__ w_im,
    const float* __restrict__ B_re, const float* __restrict__ B_im,
    const float* __restrict__ C_re, const float* __restrict__ C_im,
    const float* __restrict__ Dp,
    const float* __restrict__ Wp)
{
    extern __shared__ float sh[];
    float* u_sh  = sh;                     // 4096 floats
    float* qall  = sh + 4096;              // 8448 floats
    float* carry = qall + 8448;            // 512
    float* initv = carry + 512;            // 512

    int bid  = blockIdx.x;                 // = b*HH + h
    int h    = bid & (HH-1);
    int tid  = threadIdx.x;
    int wid  = tid >> 5, lane = tid & 31;

    // ---- folded W split: 64 elements per block ----
    if (tid < 64) {
        int wi = bid * 64 + tid;
        float w = Wp[wi];
        __nv_bfloat16 hb = __float2bfloat16(w);
        float hf = __bfloat162float(hb);
        __nv_bfloat16 lb = __float2bfloat16(w - hf);
        g_whi[wi] = __bfloat16_as_ushort(hb);
        g_wlo[wi] = __bfloat16_as_ushort(lb);
    }

    // stage u[b,h,:]
    const float4* ub4  = (const float4*)(u + (size_t)bid * LL);
    float4*       ush4 = (float4*)u_sh;
    #pragma unroll
    for (int i = tid; i < LL/4; i += 256) ush4[i] = ub4[i];

    // ---- per-warp parameter computation ----
    int pidx = (h << 5) + lane;
    float dt = __expf(log_dt[h]);
    float zr = 0.5f * dt * w_re[pidx];
    float zi = 0.5f * dt * w_im[pidx];
    float drr = 1.f - zr, dii = -zi;
    float inv = 1.f / (drr*drr + dii*dii);
    float nr = 1.f + zr, ni = zi;
    float ar = (nr*drr + ni*dii) * inv;
    float ai = (ni*drr - nr*dii) * inv;
    float brf = dt * B_re[pidx], bif = dt * B_im[pidx];
    float dbr = (brf*drr + bif*dii) * inv;
    float dbi = (bif*drr - brf*dii) * inv;
    float c2r = 2.f * C_re[pidx];
    float c2i = 2.f * C_im[pidx];

    // b_s = a^s b for s=0..3
    float bsr[4], bsi[4];
    bsr[0] = dbr; bsi[0] = dbi;
    #pragma unroll
    for (int s = 1; s < 4; s++) {
        bsr[s] = ar*bsr[s-1] - ai*bsi[s-1];
        bsi[s] = ar*bsi[s-1] + ai*bsr[s-1];
    }
    float a2r = ar*ar - ai*ai,     a2i = 2.f*ar*ai;
    float a4r = a2r*a2r - a2i*a2i, a4i = 2.f*a2r*a2i;

    // FIR scalars g_s = sum_n Re(c2 a^s b), s=0..3
    float g0f = warp_sum(c2r*bsr[0] - c2i*bsi[0]);
    float g1f = warp_sum(c2r*bsr[1] - c2i*bsi[1]);
    float g2f = warp_sum(c2r*bsr[2] - c2i*bsi[2]);
    float g3f = warp_sum(c2r*bsr[3] - c2i*bsi[3]);
    float s1  = warp_sum(dbr);
    float dcb = 2.f * s1 * g0f;

    ull Bv0 = pk(bsr[0], bsi[0]), Bv1 = pk(bsr[1], bsi[1]);
    ull Bv2 = pk(bsr[2], bsi[2]), Bv3 = pk(bsr[3], bsi[3]);
    ull A4RR = pk(a4r, a4r), A4IN = pk(-a4i, a4i);
    __syncthreads();

    int base = wid * CLEN;

    // ---- phase 1: chunk-local carry via Horner-8 (extra consts scoped) ----
    if (wid < NCH-1) {
        float a8r = a4r*a4r - a4i*a4i, a8i = 2.f*a4r*a4i;
        ull A8RR = pk(a8r, a8r), A8IN = pk(-a8i, a8i);
        ull Bw0 = pk(a4r*bsr[0] - a4i*bsi[0], a4r*bsi[0] + a4i*bsr[0]);
        ull Bw1 = pk(a4r*bsr[1] - a4i*bsi[1], a4r*bsi[1] + a4i*bsr[1]);
        ull Bw2 = pk(a4r*bsr[2] - a4i*bsi[2], a4r*bsi[2] + a4i*bsr[2]);
        ull Bw3 = pk(a4r*bsr[3] - a4i*bsi[3], a4r*bsi[3] + a4i*bsr[3]);
        ull X = pk(0.f, 0.f), Xs = pk(0.f, 0.f);
        const float4* uc4 = (const float4*)(u_sh + base);
        #pragma unroll 4
        for (int g = 0; g < CLEN/8; g++) {
            float4 ua = uc4[g*2+0];
            float4 ub = uc4[g*2+1];
            ull p = mul2(Bv0, pk(ub.w, ub.w));
            p = fma2(Bv1, pk(ub.z, ub.z), p);
            p = fma2(Bv2, pk(ub.y, ub.y), p);
            p = fma2(Bv3, pk(ub.x, ub.x), p);
            p = fma2(Bw0, pk(ua.w, ua.w), p);
            p = fma2(Bw1, pk(ua.z, ua.z), p);
            p = fma2(Bw2, pk(ua.y, ua.y), p);
            p = fma2(Bw3, pk(ua.x, ua.x), p);
            ull t = fma2(A8RR, X, p);
            X = fma2(A8IN, Xs, t);
            float xr_, xi_; upk(X, xr_, xi_);
            Xs = pk(xi_, xr_);
        }
        float xr_, xi_; upk(X, xr_, xi_);
        carry[wid*64 + lane]      = xr_;
        carry[wid*64 + 32 + lane] = xi_;
    }
    __syncthreads();

    // ---- phase 2: warp 0 prefix-combines carries with dA^CLEN ----
    if (wid == 0) {
        float pr = a4r, pi = a4i;    // a^4 -> a^512 via 7 squarings
        #pragma unroll
        for (int k = 0; k < 7; k++) { float t = pr*pr - pi*pi; pi = 2.f*pr*pi; pr = t; }
        float Xr = 0.f, Xi = 0.f;
        #pragma unroll
        for (int s = 0; s < NCH; s++) {
            initv[s*64 + lane]      = Xr;
            initv[s*64 + 32 + lane] = Xi;
            if (s < NCH-1) {
                float cr_ = carry[s*64 + lane];
                float ci_ = carry[s*64 + 32 + lane];
                float nXr = fmaf(pr, Xr, fmaf(-pi, Xi, cr_));
                float nXi = fmaf(pi, Xr, fmaf( pr, Xi, ci_));
                Xr = nXr; Xi = nXi;
            }
        }
    }
    __syncthreads();

    // ---- projection constants v_k = c2 a^k, k=1..4 ----
    float v1r = c2r*ar  - c2i*ai,  v1i = c2r*ai  + c2i*ar;
    float v2r = v1r*ar  - v1i*ai,  v2i = v1r*ai  + v1i*ar;
    float v3r = v2r*ar  - v2i*ai,  v3i = v2r*ai  + v2i*ar;
    float v4r = v3r*ar  - v3i*ai,  v4i = v3r*ai  + v3i*ar;
    ull V1 = pk(v1r, -v2i), V2 = pk(-v1i, v2r);
    ull V3 = pk(v3r, -v4i), V4 = pk(-v3i, v4r);

    // ---- phase 3: Horner-4 advance + broadcast-free projections ----
    float Dh = Dp[h];
    float xr0 = initv[wid*64 + lane];
    float xi0 = initv[wid*64 + 32 + lane];
    ull X = pk(xr0, xi0), Xs = pk(xi0, xr0);
    float* q = qall + wid * 1056;
    ush* ghi = g_ahi + (size_t)bid * LL + base;
    ush* glo = g_alo + (size_t)bid * LL + base;

    for (int t0 = 0; t0 < CLEN; t0 += 32) {
        const float4* up4 = (const float4*)(u_sh + base + t0);
        #pragma unroll
        for (int g = 0; g < 8; g++) {
            ull P01 = fma2(V1, X, mul2(V2, Xs));
            ull P23 = fma2(V3, X, mul2(V4, Xs));
            *(ull*)&q[(2*g  )*66 + 2*lane] = P01;
            *(ull*)&q[(2*g+1)*66 + 2*lane] = P23;
            float4 uu = up4[g];
            ull p = mul2(Bv0, pk(uu.w, uu.w));
            p = fma2(Bv1, pk(uu.z, uu.z), p);
            p = fma2(Bv2, pk(uu.y, uu.y), p);
            p = fma2(Bv3, pk(uu.x, uu.x), p);
            ull t = fma2(A4RR, X, p);
            X = fma2(A4IN, Xs, t);
            float xr_, xi_; upk(X, xr_, xi_);
            Xs = pk(xi_, xr_);
        }
        __syncwarp();
        int c = lane & 15, hh2 = lane >> 4;
        const float* qr = q + c*66 + hh2*32;
        ull S = *(const ull*)qr;
        #pragma unroll
        for (int n = 1; n < 16; n++) S = add2(S, *(const ull*)(qr + 2*n));
        float slo, shi; upk(S, slo, shi);
        slo += __shfl_xor_sync(0xffffffffu, slo, 16);
        shi += __shfl_xor_sync(0xffffffffu, shi, 16);
        int tloc = 2*c + hh2;
        float s = hh2 ? shi : slo;
        int l = base + t0 + tloc;
        int r = tloc & 3;
        float ul = u_sh[l];
        s = fmaf(g0f, ul, s);
        float up1 = (l > 0) ? u_sh[l-1] : 0.f;
        if (r > 0) s = fmaf(g1f, up1, s);
        if (r > 1) s = fmaf(g2f, u_sh[l-2], s);
        if (r > 2) s = fmaf(g3f, u_sh[l-3], s);
        s = fmaf(Dh, ul, s);                 // D skip
        s = fmaf(dcb * ul, up1, s);          // liquid term
        float gv = gelu_tanh(s);
        __nv_bfloat16 hb = __float2bfloat16(gv);
        float hf = __bfloat162float(hb);
        __nv_bfloat16 lb = __float2bfloat16(gv - hf);
        ghi[t0 + tloc] = __bfloat16_as_ushort(hb);
        glo[t0 + tloc] = __bfloat16_as_ushort(lb);
        __syncwarp();
    }
}

// ---------------- tensor-core GEMM via mma.sync (bf16 3-split) ------------
// 512 threads (16 warps -> 8 warps/SMSP at 2 CTA/SM), k-chunk 32, 2-stage.
// Warp tile 16o x 64l; CTA tile 128o x 128l.
#define ASTR 40     // A smem row stride (ushorts), 32 k + 8 pad
#define BSTR 136    // B smem row stride (ushorts)
#define AHSZ (128*ASTR)     // 5120 ush
#define BHSZ (32*BSTR)      // 4352 ush
#define AH_OFF(bf) ((bf)*AHSZ)
#define AL_OFF(bf) (2*AHSZ + (bf)*AHSZ)
#define BH_OFF(bf) (4*AHSZ + (bf)*BHSZ)
#define BL_OFF(bf) (4*AHSZ + 2*BHSZ + (bf)*BHSZ)
#define GSMEM_USH  (4*AHSZ + 4*BHSZ)      // 37888 ush = 75776 B

__device__ __forceinline__ void ldsm4(unsigned* r, uint32_t addr) {
    asm volatile("ldmatrix.sync.aligned.m8n8.x4.shared.b16 {%0,%1,%2,%3}, [%4];"
        : "=r"(r[0]), "=r"(r[1]), "=r"(r[2]), "=r"(r[3]) : "r"(addr));
}
__device__ __forceinline__ void ldsm4t(unsigned* r, uint32_t addr) {
    asm volatile("ldmatrix.sync.aligned.m8n8.x4.trans.shared.b16 {%0,%1,%2,%3}, [%4];"
        : "=r"(r[0]), "=r"(r[1]), "=r"(r[2]), "=r"(r[3]) : "r"(addr));
}
__device__ __forceinline__ void mma_bf(float* c, const unsigned* a, const unsigned* b) {
    asm volatile("mma.sync.aligned.m16n8k16.row.col.f32.bf16.bf16.f32 "
        "{%0,%1,%2,%3}, {%4,%5,%6,%7}, {%8,%9}, {%0,%1,%2,%3};"
        : "+f"(c[0]), "+f"(c[1]), "+f"(c[2]), "+f"(c[3])
        : "r"(a[0]), "r"(a[1]), "r"(a[2]), "r"(a[3]), "r"(b[0]), "r"(b[1]));
}
#define CP16(dst, src) asm volatile("cp.async.cg.shared.global [%0], [%1], 16;" \
                                    :: "r"(dst), "l"(src))
#define CP_COMMIT() asm volatile("cp.async.commit_group;")

__global__ void __launch_bounds__(512, 2) tgemm_kernel(const float* __restrict__ bias,
                                                       float* __restrict__ out)
{
    extern __shared__ ush tsm[];
    uint32_t smb = smem_u32(tsm);

    int tid = threadIdx.x, wid = tid >> 5, lane = tid & 31;
    int l0 = blockIdx.x * 128, o0 = blockIdx.y * 128, b = blockIdx.z;
    int wo = wid >> 1, wl = wid & 1;      // wo: 0..7 (16 o-rows each), wl: 0..1

    const ush* acth = g_ahi + (size_t)b * HH * LL;
    const ush* actl = g_alo + (size_t)b * HH * LL;

    int mat = lane >> 3, mrow = lane & 7;
    int laneA = ((mat & 1) * 8 + mrow) * ASTR + (mat >> 1) * 8;
    int laneB = ((mat & 1) * 8 + mrow) * BSTR + (mat >> 1) * 8;

    #define STAGE(bf, k0) { \
        _Pragma("unroll") \
        for (int i_ = 0; i_ < 2; i_++) { \
            int idx = tid + i_ * 512; \
            int row = idx >> 3, rem = idx & 7, ch = rem >> 1, sp = rem & 1; \
            const ush* src = (sp ? g_wlo : g_whi) + (size_t)(o0 + row) * HH + (k0) + ch * 8; \
            uint32_t dst = smb + ((sp ? AL_OFF(bf) : AH_OFF(bf)) + row * ASTR + ch * 8) * 2; \
            CP16(dst, src); \
        } \
        _Pragma("unroll") \
        for (int i_ = 0; i_ < 2; i_++) { \
            int idx = tid + i_ * 512; \
            int row = idx >> 5, rem = idx & 31, ch = rem >> 1, sp = rem & 1; \
            const ush* src = (sp ? actl : acth) + (size_t)((k0) + row) * LL + l0 + ch * 8; \
            uint32_t dst = smb + ((sp ? BL_OFF(bf) : BH_OFF(bf)) + row * BSTR + ch * 8) * 2; \
            CP16(dst, src); \
        } }

    float acc[8][4];
    #pragma unroll
    for (int nt = 0; nt < 8; nt++)
        #pragma unroll
        for (int j = 0; j < 4; j++) acc[nt][j] = 0.f;

    STAGE(0, 0);
    CP_COMMIT();

    for (int kt = 0; kt < 8; kt++) {
        int bf = kt & 1;
        if (kt < 7) {
            STAGE(bf ^ 1, (kt + 1) * 32);
            CP_COMMIT();
            asm volatile("cp.async.wait_group 1;");
        } else {
            asm volatile("cp.async.wait_group 0;");
        }
        __syncthreads();

        uint32_t ah = smb + AH_OFF(bf) * 2, al = smb + AL_OFF(bf) * 2;
        uint32_t bh = smb + BH_OFF(bf) * 2, bl = smb + BL_OFF(bf) * 2;
        #pragma unroll
        for (int ks = 0; ks < 2; ks++) {
            unsigned afh[4], afl[4];
            {
                int toff = ((wo * 16) * ASTR + ks * 16 + laneA) * 2;
                ldsm4(afh, ah + toff);
                ldsm4(afl, al + toff);
            }
            #pragma unroll
            for (int nc = 0; nc < 4; nc++) {
                unsigned bfh[4], bfl[4];
                int boff = (ks * 16 * BSTR + wl * 64 + nc * 16 + laneB) * 2;
                ldsm4t(bfh, bh + boff);
                ldsm4t(bfl, bl + boff);
                // hh (2 independent accs), hl, lh
                mma_bf(acc[nc*2],   afh, bfh);
                mma_bf(acc[nc*2+1], afh, bfh + 2);
                mma_bf(acc[nc*2],   afh, bfl);
                mma_bf(acc[nc*2+1], afh, bfl + 2);
                mma_bf(acc[nc*2],   afl, bfh);
                mma_bf(acc[nc*2+1], afl, bfh + 2);
            }
        }
        __syncthreads();
    }

    // epilogue: warp writes 16 o-rows x 64 l-cols
    int m_ = o0 + wo * 16 + (lane >> 2);
    float bv0 = bias[m_], bv1 = bias[m_ + 8];
    float* r0p = out + ((size_t)(b * HH + m_)) * LL;
    float* r1p = r0p + 8 * LL;
    #pragma unroll
    for (int nt = 0; nt < 8; nt++) {
        int n_ = l0 + wl * 64 + nt * 8 + (lane & 3) * 2;
        float2 v0, v1;
        v0.x = acc[nt][0] + bv0; v0.y = acc[nt][1] + bv0;
        v1.x = acc[nt][2] + bv1; v1.y = acc[nt][3] + bv1;
        *(float2*)(r0p + n_) = v0;
        *(float2*)(r1p + n_) = v1;
    }
}

// ---------------------------- launch --------------------------------------
extern "C" void kernel_launch(void* const* d_in, const int* in_sizes, int n_in,
                              void* d_out, int out_size)
{
    const float* u      = (const float*)d_in[0];
    const float* log_dt = (const float*)d_in[1];
    const float* w_re   = (const float*)d_in[2];
    const float* w_im   = (const float*)d_in[3];
    const float* B_re   = (const float*)d_in[4];
    const float* B_im   = (const float*)d_in[5];
    const float* C_re   = (const float*)d_in[6];
    const float* C_im   = (const float*)d_in[7];
    const float* D      = (const float*)d_in[8];
    const float* W      = (const float*)d_in[9];
    const float* bias   = (const float*)d_in[10];
    float* out = (float*)d_out;

    int smem = (4096 + 8448 + 512 + 512) * (int)sizeof(float);   // 54272 B
    cudaFuncSetAttribute(scan_kernel, cudaFuncAttributeMaxDynamicSharedMemorySize, smem);
    scan_kernel<<<BB*HH, 256, smem>>>(u, log_dt, w_re, w_im, B_re, B_im,
                                      C_re, C_im, D, W);

    int gsmem = GSMEM_USH * (int)sizeof(ush);   // 75776 B
    cudaFuncSetAttribute(tgemm_kernel, cudaFuncAttributeMaxDynamicSharedMemorySize, gsmem);
    tgemm_kernel<<<dim3(LL/128, HH/128, BB), 512, gsmem>>>(bias, out);
}

// round 17
// speedup vs baseline: 1.0989x; 1.0989x over previous
#include <cuda_runtime.h>
#include <cuda_fp16.h>
#include <cstdint>

#define HH   256
#define NN   32
#define LL   4096
#define BB   4
#define NCH  8
#define CLEN 512   // LL / NCH

typedef unsigned long long ull;
typedef unsigned short ush;

// ---------------- device scratch (no allocations allowed) ----------------
__device__ ush g_act[(size_t)BB*HH*LL];   // act fp16, [b][h][l]
__device__ ush g_whi[HH*HH];              // W fp16 hi, [o][h]
__device__ ush g_wlo[HH*HH];              // W fp16 lo

// ---------------- packed f32x2 helpers ----------------
__device__ __forceinline__ ull pk(float lo, float hi) {
    ull r;
    asm("mov.b64 %0, {%1, %2};" : "=l"(r)
        : "r"(__float_as_uint(lo)), "r"(__float_as_uint(hi)));
    return r;
}
__device__ __forceinline__ void upk(ull v, float& lo, float& hi) {
    unsigned a, b;
    asm("mov.b64 {%0, %1}, %2;" : "=r"(a), "=r"(b) : "l"(v));
    lo = __uint_as_float(a); hi = __uint_as_float(b);
}
__device__ __forceinline__ ull fma2(ull a, ull b, ull c) {
    ull d;
    asm("fma.rn.f32x2 %0, %1, %2, %3;" : "=l"(d) : "l"(a), "l"(b), "l"(c));
    return d;
}
__device__ __forceinline__ ull mul2(ull a, ull b) {
    ull d;
    asm("mul.rn.f32x2 %0, %1, %2;" : "=l"(d) : "l"(a), "l"(b));
    return d;
}
__device__ __forceinline__ ull add2(ull a, ull b) {
    ull d;
    asm("add.rn.f32x2 %0, %1, %2;" : "=l"(d) : "l"(a), "l"(b));
    return d;
}

__device__ __forceinline__ float gelu_tanh(float x)
{
    float x3 = x * x * x;
    float z  = 0.7978845608028654f * fmaf(0.044715f, x3, x);
    float e  = __expf(2.f * z);
    float t  = 1.f - __fdividef(2.f, e + 1.f);   // tanh(z)
    return 0.5f * x * (1.f + t);
}

__device__ __forceinline__ float warp_sum(float v) {
    #pragma unroll
    for (int m = 16; m >= 1; m >>= 1) v += __shfl_xor_sync(0xffffffffu, v, m);
    return v;
}

__device__ __forceinline__ uint32_t smem_u32(const void* p) {
    uint32_t a;
    asm("{ .reg .u64 t; cvta.to.shared.u64 t, %1; cvt.u32.u64 %0, t; }"
        : "=r"(a) : "l"(p));
    return a;
}

// ---------------- fused scan + W split + D + liquid + gelu ----------------
// SMEM: u (4096 f) | q (8 warps * 1056 f) | carry 512 | initv 512 = 54272 B
__global__ void __launch_bounds__(256, 4) scan_kernel(
    const float* __restrict__ u,
    const float* __restrict__ log_dt,
    const float* __restrict__ w_re, const float* __restrict__ w_im,
    const float* __restrict__ B_re, const float* __restrict__ B_im,
    const float* __restrict__ C_re, const float* __restrict__ C_im,
    const float* __restrict__ Dp,
    const float* __restrict__ Wp)
{
    extern __shared__ float sh[];
    float* u_sh  = sh;                     // 4096 floats
    float* qall  = sh + 4096;              // 8448 floats
    float* carry = qall + 8448;            // 512
    float* initv = carry + 512;            // 512

    int bid  = blockIdx.x;                 // = b*HH + h
    int h    = bid & (HH-1);
    int tid  = threadIdx.x;
    int wid  = tid >> 5, lane = tid & 31;

    // ---- folded W split (fp16 hi/lo): 64 elements per block ----
    if (tid < 64) {
        int wi = bid * 64 + tid;
        float w = Wp[wi];
        __half hb = __float2half(w);
        float hf = __half2float(hb);
        __half lb = __float2half(w - hf);
        g_whi[wi] = __half_as_ushort(hb);
        g_wlo[wi] = __half_as_ushort(lb);
    }

    // stage u[b,h,:]
    const float4* ub4  = (const float4*)(u + (size_t)bid * LL);
    float4*       ush4 = (float4*)u_sh;
    #pragma unroll
    for (int i = tid; i < LL/4; i += 256) ush4[i] = ub4[i];

    // ---- per-warp parameter computation ----
    int pidx = (h << 5) + lane;
    float dt = __expf(log_dt[h]);
    float zr = 0.5f * dt * w_re[pidx];
    float zi = 0.5f * dt * w_im[pidx];
    float drr = 1.f - zr, dii = -zi;
    float inv = 1.f / (drr*drr + dii*dii);
    float nr = 1.f + zr, ni = zi;
    float ar = (nr*drr + ni*dii) * inv;
    float ai = (ni*drr - nr*dii) * inv;
    float brf = dt * B_re[pidx], bif = dt * B_im[pidx];
    float dbr = (brf*drr + bif*dii) * inv;
    float dbi = (bif*drr - brf*dii) * inv;
    float c2r = 2.f * C_re[pidx];
    float c2i = 2.f * C_im[pidx];

    // b_s = a^s b for s=0..3
    float bsr[4], bsi[4];
    bsr[0] = dbr; bsi[0] = dbi;
    #pragma unroll
    for (int s = 1; s < 4; s++) {
        bsr[s] = ar*bsr[s-1] - ai*bsi[s-1];
        bsi[s] = ar*bsi[s-1] + ai*bsr[s-1];
    }
    float a2r = ar*ar - ai*ai,     a2i = 2.f*ar*ai;
    float a4r = a2r*a2r - a2i*a2i, a4i = 2.f*a2r*a2i;

    // FIR scalars g_s = sum_n Re(c2 a^s b), s=0..3
    float g0f = warp_sum(c2r*bsr[0] - c2i*bsi[0]);
    float g1f = warp_sum(c2r*bsr[1] - c2i*bsi[1]);
    float g2f = warp_sum(c2r*bsr[2] - c2i*bsi[2]);
    float g3f = warp_sum(c2r*bsr[3] - c2i*bsi[3]);
    float s1  = warp_sum(dbr);
    float dcb = 2.f * s1 * g0f;

    ull Bv0 = pk(bsr[0], bsi[0]), Bv1 = pk(bsr[1], bsi[1]);
    ull Bv2 = pk(bsr[2], bsi[2]), Bv3 = pk(bsr[3], bsi[3]);
    ull A4RR = pk(a4r, a4r), A4IN = pk(-a4i, a4i);
    __syncthreads();

    int base = wid * CLEN;

    // ---- phase 1: chunk-local carry via Horner-8 (extra consts scoped) ----
    if (wid < NCH-1) {
        float a8r = a4r*a4r - a4i*a4i, a8i = 2.f*a4r*a4i;
        ull A8RR = pk(a8r, a8r), A8IN = pk(-a8i, a8i);
        ull Bw0 = pk(a4r*bsr[0] - a4i*bsi[0], a4r*bsi[0] + a4i*bsr[0]);
        ull Bw1 = pk(a4r*bsr[1] - a4i*bsi[1], a4r*bsi[1] + a4i*bsr[1]);
        ull Bw2 = pk(a4r*bsr[2] - a4i*bsi[2], a4r*bsi[2] + a4i*bsr[2]);
        ull Bw3 = pk(a4r*bsr[3] - a4i*bsi[3], a4r*bsi[3] + a4i*bsr[3]);
        ull X = pk(0.f, 0.f), Xs = pk(0.f, 0.f);
        const float4* uc4 = (const float4*)(u_sh + base);
        #pragma unroll 4
        for (int g = 0; g < CLEN/8; g++) {
            float4 ua = uc4[g*2+0];
            float4 ub = uc4[g*2+1];
            ull p = mul2(Bv0, pk(ub.w, ub.w));
            p = fma2(Bv1, pk(ub.z, ub.z), p);
            p = fma2(Bv2, pk(ub.y, ub.y), p);
            p = fma2(Bv3, pk(ub.x, ub.x), p);
            p = fma2(Bw0, pk(ua.w, ua.w), p);
            p = fma2(Bw1, pk(ua.z, ua.z), p);
            p = fma2(Bw2, pk(ua.y, ua.y), p);
            p = fma2(Bw3, pk(ua.x, ua.x), p);
            ull t = fma2(A8RR, X, p);
            X = fma2(A8IN, Xs, t);
            float xr_, xi_; upk(X, xr_, xi_);
            Xs = pk(xi_, xr_);
        }
        float xr_, xi_; upk(X, xr_, xi_);
        carry[wid*64 + lane]      = xr_;
        carry[wid*64 + 32 + lane] = xi_;
    }
    __syncthreads();

    // ---- phase 2: warp 0 prefix-combines carries with dA^CLEN ----
    if (wid == 0) {
        float pr = a4r, pi = a4i;    // a^4 -> a^512 via 7 squarings
        #pragma unroll
        for (int k = 0; k < 7; k++) { float t = pr*pr - pi*pi; pi = 2.f*pr*pi; pr = t; }
        float Xr = 0.f, Xi = 0.f;
        #pragma unroll
        for (int s = 0; s < NCH; s++) {
            initv[s*64 + lane]      = Xr;
            initv[s*64 + 32 + lane] = Xi;
            if (s < NCH-1) {
                float cr_ = carry[s*64 + lane];
                float ci_ = carry[s*64 + 32 + lane];
                float nXr = fmaf(pr, Xr, fmaf(-pi, Xi, cr_));
                float nXi = fmaf(pi, Xr, fmaf( pr, Xi, ci_));
                Xr = nXr; Xi = nXi;
            }
        }
    }
    __syncthreads();

    // ---- projection constants v_k = c2 a^k, k=1..4 ----
    float v1r = c2r*ar  - c2i*ai,  v1i = c2r*ai  + c2i*ar;
    float v2r = v1r*ar  - v1i*ai,  v2i = v1r*ai  + v1i*ar;
    float v3r = v2r*ar  - v2i*ai,  v3i = v2r*ai  + v2i*ar;
    float v4r = v3r*ar  - v3i*ai,  v4i = v3r*ai  + v3i*ar;
    ull V1 = pk(v1r, -v2i), V2 = pk(-v1i, v2r);
    ull V3 = pk(v3r, -v4i), V4 = pk(-v3i, v4r);

    // ---- phase 3: Horner-4 advance + broadcast-free projections ----
    float Dh = Dp[h];
    float xr0 = initv[wid*64 + lane];
    float xi0 = initv[wid*64 + 32 + lane];
    ull X = pk(xr0, xi0), Xs = pk(xi0, xr0);
    float* q = qall + wid * 1056;
    ush* gout = g_act + (size_t)bid * LL + base;

    for (int t0 = 0; t0 < CLEN; t0 += 32) {
        const float4* up4 = (const float4*)(u_sh + base + t0);
        #pragma unroll
        for (int g = 0; g < 8; g++) {
            ull P01 = fma2(V1, X, mul2(V2, Xs));
            ull P23 = fma2(V3, X, mul2(V4, Xs));
            *(ull*)&q[(2*g  )*66 + 2*lane] = P01;
            *(ull*)&q[(2*g+1)*66 + 2*lane] = P23;
            float4 uu = up4[g];
            ull p = mul2(Bv0, pk(uu.w, uu.w));
            p = fma2(Bv1, pk(uu.z, uu.z), p);
            p = fma2(Bv2, pk(uu.y, uu.y), p);
            p = fma2(Bv3, pk(uu.x, uu.x), p);
            ull t = fma2(A4RR, X, p);
            X = fma2(A4IN, Xs, t);
            float xr_, xi_; upk(X, xr_, xi_);
            Xs = pk(xi_, xr_);
        }
        __syncwarp();
        int c = lane & 15, hh2 = lane >> 4;
        const float* qr = q + c*66 + hh2*32;
        ull S = *(const ull*)qr;
        #pragma unroll
        for (int n = 1; n < 16; n++) S = add2(S, *(const ull*)(qr + 2*n));
        float slo, shi; upk(S, slo, shi);
        slo += __shfl_xor_sync(0xffffffffu, slo, 16);
        shi += __shfl_xor_sync(0xffffffffu, shi, 16);
        int tloc = 2*c + hh2;
        float s = hh2 ? shi : slo;
        int l = base + t0 + tloc;
        int r = tloc & 3;
        float ul = u_sh[l];
        s = fmaf(g0f, ul, s);
        float up1 = (l > 0) ? u_sh[l-1] : 0.f;
        if (r > 0) s = fmaf(g1f, up1, s);
        if (r > 1) s = fmaf(g2f, u_sh[l-2], s);
        if (r > 2) s = fmaf(g3f, u_sh[l-3], s);
        s = fmaf(Dh, ul, s);                 // D skip
        s = fmaf(dcb * ul, up1, s);          // liquid term
        float gv = gelu_tanh(s);
        gout[t0 + tloc] = __half_as_ushort(__float2half(gv));
        __syncwarp();
    }
}

// ---------------- tensor-core GEMM via mma.sync (fp16 2-split) ------------
// W = W_hi + W_lo (fp16 planes); G single fp16 plane. 2 MMA combos (hh, lh).
// 256 threads, warp tile 32o x 64l, k-chunk 32, 2-stage double buffer.
#define ASTR 40     // A smem row stride (ushorts), 32 k + 8 pad
#define BSTR 136    // B smem row stride (ushorts)
#define AHSZ (128*ASTR)     // 5120 ush
#define BHSZ (32*BSTR)      // 4352 ush
#define AH_OFF(bf) ((bf)*AHSZ)
#define AL_OFF(bf) (2*AHSZ + (bf)*AHSZ)
#define B_OFF(bf)  (4*AHSZ + (bf)*BHSZ)
#define GSMEM_USH  (4*AHSZ + 2*BHSZ)      // 29184 ush = 58368 B

__device__ __forceinline__ void ldsm4(unsigned* r, uint32_t addr) {
    asm volatile("ldmatrix.sync.aligned.m8n8.x4.shared.b16 {%0,%1,%2,%3}, [%4];"
        : "=r"(r[0]), "=r"(r[1]), "=r"(r[2]), "=r"(r[3]) : "r"(addr));
}
__device__ __forceinline__ void ldsm4t(unsigned* r, uint32_t addr) {
    asm volatile("ldmatrix.sync.aligned.m8n8.x4.trans.shared.b16 {%0,%1,%2,%3}, [%4];"
        : "=r"(r[0]), "=r"(r[1]), "=r"(r[2]), "=r"(r[3]) : "r"(addr));
}
__device__ __forceinline__ void mma_f16(float* c, const unsigned* a, const unsigned* b) {
    asm volatile("mma.sync.aligned.m16n8k16.row.col.f32.f16.f16.f32 "
        "{%0,%1,%2,%3}, {%4,%5,%6,%7}, {%8,%9}, {%0,%1,%2,%3};"
        : "+f"(c[0]), "+f"(c[1]), "+f"(c[2]), "+f"(c[3])
        : "r"(a[0]), "r"(a[1]), "r"(a[2]), "r"(a[3]), "r"(b[0]), "r"(b[1]));
}
#define CP16(dst, src) asm volatile("cp.async.cg.shared.global [%0], [%1], 16;" \
                                    :: "r"(dst), "l"(src))
#define CP_COMMIT() asm volatile("cp.async.commit_group;")

__global__ void __launch_bounds__(256, 2) tgemm_kernel(const float* __restrict__ bias,
                                                       float* __restrict__ out)
{
    extern __shared__ ush tsm[];
    uint32_t smb = smem_u32(tsm);

    int tid = threadIdx.x, wid = tid >> 5, lane = tid & 31;
    int l0 = blockIdx.x * 128, o0 = blockIdx.y * 128, b = blockIdx.z;
    int wo = wid >> 1, wl = wid & 1;

    const ush* act = g_act + (size_t)b * HH * LL;

    int mat = lane >> 3, mrow = lane & 7;
    int laneA = ((mat & 1) * 8 + mrow) * ASTR + (mat >> 1) * 8;
    int laneB = ((mat & 1) * 8 + mrow) * BSTR + (mat >> 1) * 8;

    // staging per k-chunk: A = 1024 vec16 (128 rows x 4 chunks x 2 planes),
    //                      B = 512 vec16 (32 rows x 16 chunks)
    #define STAGE(bf, k0) { \
        _Pragma("unroll") \
        for (int i_ = 0; i_ < 4; i_++) { \
            int idx = tid + i_ * 256; \
            int row = idx >> 3, rem = idx & 7, ch = rem >> 1, sp = rem & 1; \
            const ush* src = (sp ? g_wlo : g_whi) + (size_t)(o0 + row) * HH + (k0) + ch * 8; \
            uint32_t dst = smb + ((sp ? AL_OFF(bf) : AH_OFF(bf)) + row * ASTR + ch * 8) * 2; \
            CP16(dst, src); \
        } \
        _Pragma("unroll") \
        for (int i_ = 0; i_ < 2; i_++) { \
            int idx = tid + i_ * 256; \
            int row = idx >> 4, ch = idx & 15; \
            const ush* src = act + (size_t)((k0) + row) * LL + l0 + ch * 8; \
            uint32_t dst = smb + (B_OFF(bf) + row * BSTR + ch * 8) * 2; \
            CP16(dst, src); \
        } }

    float acc[2][8][4];
    #pragma unroll
    for (int mt = 0; mt < 2; mt++)
        #pragma unroll
        for (int nt = 0; nt < 8; nt++)
            #pragma unroll
            for (int j = 0; j < 4; j++) acc[mt][nt][j] = 0.f;

    STAGE(0, 0);
    CP_COMMIT();

    for (int kt = 0; kt < 8; kt++) {
        int bf = kt & 1;
        if (kt < 7) {
            STAGE(bf ^ 1, (kt + 1) * 32);
            CP_COMMIT();
            asm volatile("cp.async.wait_group 1;");
        } else {
            asm volatile("cp.async.wait_group 0;");
        }
        __syncthreads();

        uint32_t ah = smb + AH_OFF(bf) * 2, al = smb + AL_OFF(bf) * 2;
        uint32_t bb = smb + B_OFF(bf) * 2;
        #pragma unroll
        for (int ks = 0; ks < 2; ks++) {
            unsigned afh[2][4], afl[2][4];
            #pragma unroll
            for (int mt = 0; mt < 2; mt++) {
                int toff = ((wo * 32 + mt * 16) * ASTR + ks * 16 + laneA) * 2;
                ldsm4(afh[mt], ah + toff);
                ldsm4(afl[mt], al + toff);
            }
            #pragma unroll
            for (int nc = 0; nc < 4; nc++) {
                unsigned bfr[4];
                int boff = (ks * 16 * BSTR + wl * 64 + nc * 16 + laneB) * 2;
                ldsm4t(bfr, bb + boff);
                // W_hi * G (4 independent accs), then W_lo * G
                mma_f16(acc[0][nc*2],   afh[0], bfr);
                mma_f16(acc[0][nc*2+1], afh[0], bfr + 2);
                mma_f16(acc[1][nc*2],   afh[1], bfr);
                mma_f16(acc[1][nc*2+1], afh[1], bfr + 2);
                mma_f16(acc[0][nc*2],   afl[0], bfr);
                mma_f16(acc[0][nc*2+1], afl[0], bfr + 2);
                mma_f16(acc[1][nc*2],   afl[1], bfr);
                mma_f16(acc[1][nc*2+1], afl[1], bfr + 2);
            }
        }
        __syncthreads();
    }

    #pragma unroll
    for (int mt = 0; mt < 2; mt++) {
        int m_ = o0 + wo * 32 + mt * 16 + (lane >> 2);
        float bv0 = bias[m_], bv1 = bias[m_ + 8];
        float* r0p = out + ((size_t)(b * HH + m_)) * LL;
        float* r1p = r0p + 8 * LL;
        #pragma unroll
        for (int nt = 0; nt < 8; nt++) {
            int n_ = l0 + wl * 64 + nt * 8 + (lane & 3) * 2;
            float2 v0, v1;
            v0.x = acc[mt][nt][0] + bv0; v0.y = acc[mt][nt][1] + bv0;
            v1.x = acc[mt][nt][2] + bv1; v1.y = acc[mt][nt][3] + bv1;
            *(float2*)(r0p + n_) = v0;
            *(float2*)(r1p + n_) = v1;
        }
    }
}

// ---------------------------- launch --------------------------------------
extern "C" void kernel_launch(void* const* d_in, const int* in_sizes, int n_in,
                              void* d_out, int out_size)
{
    const float* u      = (const float*)d_in[0];
    const float* log_dt = (const float*)d_in[1];
    const float* w_re   = (const float*)d_in[2];
    const float* w_im   = (const float*)d_in[3];
    const float* B_re   = (const float*)d_in[4];
    const float* B_im   = (const float*)d_in[5];
    const float* C_re   = (const float*)d_in[6];
    const float* C_im   = (const float*)d_in[7];
    const float* D      = (const float*)d_in[8];
    const float* W      = (const float*)d_in[9];
    const float* bias   = (const float*)d_in[10];
    float* out = (float*)d_out;

    int smem = (4096 + 8448 + 512 + 512) * (int)sizeof(float);   // 54272 B
    cudaFuncSetAttribute(scan_kernel, cudaFuncAttributeMaxDynamicSharedMemorySize, smem);
    scan_kernel<<<BB*HH, 256, smem>>>(u, log_dt, w_re, w_im, B_re, B_im,
                                      C_re, C_im, D, W);

    int gsmem = GSMEM_USH * (int)sizeof(ush);   // 58368 B
    cudaFuncSetAttribute(tgemm_kernel, cudaFuncAttributeMaxDynamicSharedMemorySize, gsmem);
    tgemm_kernel<<<dim3(LL/128, HH/128, BB), 256, gsmem>>>(bias, out);
}